// round 14
// baseline (speedup 1.0000x reference)
#include <cuda_runtime.h>
#include <cuda_bf16.h>
#include <cstdint>

using bf16  = __nv_bfloat16;
using bf162 = __nv_bfloat162;

static constexpr int Bb = 32, Cc = 512, Nn = 1024, C3 = 1536;

// ---------------- device scratch ----------------
__device__ __align__(16) float g_ga[Bb * Cc];
__device__ __align__(16) float g_gb[Bb * Cc];
__device__ __align__(16) bf16  g_w1b[C3 * Cc];
__device__ __align__(16) bf16  g_w2b[Cc * Cc];
__device__ __align__(16) bf16  g_xnT [(size_t)Bb * Nn * Cc];
__device__ __align__(16) bf16  g_qkv [(size_t)Bb * C3 * Nn];
__device__ __align__(16) bf16  g_E   [(size_t)Bb * Nn * Nn];
__device__ __align__(16) float g_psum[(size_t)Bb * Nn * 8];
__device__ __align__(16) bf16  g_attn[(size_t)Bb * Nn * Cc];

// ---------------- PTX helpers ----------------
__device__ __forceinline__ uint32_t smem_u32(const void* p) {
    return (uint32_t)__cvta_generic_to_shared(p);
}
__device__ __forceinline__ void cp_async16(uint32_t s, const void* g) {
    asm volatile("cp.async.cg.shared.global [%0], [%1], 16;\n" :: "r"(s), "l"(g));
}
__device__ __forceinline__ void cp_commit() {
    asm volatile("cp.async.commit_group;\n" ::: "memory");
}
template <int N>
__device__ __forceinline__ void cp_wait() {
    asm volatile("cp.async.wait_group %0;\n" :: "n"(N) : "memory");
}
__device__ __forceinline__ void ldsm_x4(uint32_t* r, uint32_t addr) {
    asm volatile("ldmatrix.sync.aligned.m8n8.x4.shared.b16 {%0,%1,%2,%3}, [%4];\n"
                 : "=r"(r[0]), "=r"(r[1]), "=r"(r[2]), "=r"(r[3]) : "r"(addr));
}
__device__ __forceinline__ void ldsm_x4_t(uint32_t* r, uint32_t addr) {
    asm volatile("ldmatrix.sync.aligned.m8n8.x4.trans.shared.b16 {%0,%1,%2,%3}, [%4];\n"
                 : "=r"(r[0]), "=r"(r[1]), "=r"(r[2]), "=r"(r[3]) : "r"(addr));
}
__device__ __forceinline__ void mma_16816(float* d, const uint32_t* a,
                                          uint32_t b0, uint32_t b1) {
    asm volatile("mma.sync.aligned.m16n8k16.row.col.f32.bf16.bf16.f32 "
                 "{%0,%1,%2,%3}, {%4,%5,%6,%7}, {%8,%9}, {%0,%1,%2,%3};\n"
                 : "+f"(d[0]), "+f"(d[1]), "+f"(d[2]), "+f"(d[3])
                 : "r"(a[0]), "r"(a[1]), "r"(a[2]), "r"(a[3]), "r"(b0), "r"(b1));
}

// ---------------- bf16 GEMM: D[M,N] = A[M,K] @ B[N,K]^T ----------
// Tile BM x BN_ (BN_ in {64,128}), 256 threads, 2x4 warps, BK=64, 3 stages.
// EPI: 0 = bf16 + bias[row], 3 = f32 + bias[row] + resid,
//      5 = bf16 scaled by 1/rowsum (bias = psum[b][row][8] partials)
static constexpr int BM = 128, BK = 64, PAD = 8, NST = 3;
static constexpr int LDT = BK + PAD;
static constexpr int SAe = BM * LDT;                   // A elems per stage
template <int BN_> struct GCfg {
    static constexpr int SBe = BN_ * LDT;              // B elems per stage
    static constexpr int SMEM = NST * (SAe + SBe) * 2; // bytes
};

template <int EPI, int BN_>
__global__ __launch_bounds__(256) void gemm_bt(
        const bf16* __restrict__ A, const bf16* __restrict__ B, void* __restrict__ C,
        const float* __restrict__ bias, const float* __restrict__ resid,
        int M, int N, int K, int ldA, int ldB, int ldC,
        long sA, long sB, long sC, long sR) {
    constexpr int NT  = BN_ / 32;   // nt loop count per warp
    constexpr int NRG = BN_ / 64;   // B ldsm count per ks
    constexpr int SBe = GCfg<BN_>::SBe;
    extern __shared__ bf16 sm[];
    bf16* AsAll = sm;
    bf16* BsAll = sm + NST * SAe;

    const int tid = threadIdx.x, lane = tid & 31, wid = tid >> 5;
    const int wm = wid & 1, wn = wid >> 1;
    const int m0 = blockIdx.y * BM, n0 = blockIdx.x * BN_, bz = blockIdx.z;
    A += (size_t)bz * sA;
    B += (size_t)bz * sB;

    float acc[4][NT][4];
    #pragma unroll
    for (int i = 0; i < 4; ++i)
        #pragma unroll
        for (int j = 0; j < NT; ++j)
            #pragma unroll
            for (int k = 0; k < 4; ++k) acc[i][j][k] = 0.f;

    const int lr = tid >> 3, lc = (tid & 7) * 8;

    auto load_stage = [&](int kt, int s) {
        bf16* As = AsAll + s * SAe;
        bf16* Bs = BsAll + s * SBe;
        const bf16* Ag = A + (size_t)m0 * ldA + kt * BK;
        const bf16* Bg = B + (size_t)n0 * ldB + kt * BK;
        #pragma unroll
        for (int i = 0; i < 4; ++i) {
            int r = lr + i * 32;
            cp_async16(smem_u32(As + r * LDT + lc), Ag + (size_t)r * ldA + lc);
        }
        #pragma unroll
        for (int i = 0; i < BN_ / 32; ++i) {
            int r = lr + i * 32;
            cp_async16(smem_u32(Bs + r * LDT + lc), Bg + (size_t)r * ldB + lc);
        }
        cp_commit();
    };

    const int KT = K / BK;
    load_stage(0, 0);
    load_stage(1, 1);

    int sIdx = 0;
    for (int kt = 0; kt < KT; ++kt) {
        if (kt == KT - 1) cp_wait<0>(); else cp_wait<1>();
        __syncthreads();
        if (kt + 2 < KT) {
            int ns = sIdx + 2; if (ns >= NST) ns -= NST;
            load_stage(kt + 2, ns);
        }

        const bf16* As = AsAll + sIdx * SAe;
        const bf16* Bs = BsAll + sIdx * SBe;
        uint32_t aAddr = smem_u32(As + (wm * 64 + (lane & 15)) * LDT + (lane >> 4) * 8);
        uint32_t bAddr = smem_u32(Bs + (wn * (BN_ / 4) + (lane & 15)) * LDT
                                     + (lane >> 4) * 8);

        #pragma unroll
        for (int ks = 0; ks < 4; ++ks) {
            uint32_t ar[4][4], br[NRG][4];
            #pragma unroll
            for (int mt = 0; mt < 4; ++mt)
                ldsm_x4(ar[mt], aAddr + (uint32_t)(mt * 16 * LDT + ks * 16) * 2);
            #pragma unroll
            for (int rg = 0; rg < NRG; ++rg)
                ldsm_x4(br[rg], bAddr + (uint32_t)(rg * 16 * LDT + ks * 16) * 2);
            #pragma unroll
            for (int mt = 0; mt < 4; ++mt)
                #pragma unroll
                for (int nt = 0; nt < NT; ++nt)
                    mma_16816(acc[mt][nt], ar[mt],
                              br[nt >> 1][nt & 1], br[nt >> 1][(nt & 1) + 2]);
        }
        ++sIdx; if (sIdx >= NST) sIdx = 0;
    }

    const int g = lane >> 2, tc = lane & 3;
    #pragma unroll
    for (int mt = 0; mt < 4; ++mt) {
        int row = m0 + wm * 64 + mt * 16 + g;
        float bv0 = 0.f, bv1 = 0.f;
        if constexpr (EPI == 0 || EPI == 3) { bv0 = bias[row]; bv1 = bias[row + 8]; }
        float inv0 = 1.f, inv1 = 1.f;
        if constexpr (EPI == 5) {
            const float* p0 = bias + ((size_t)bz * Nn + row) * 8;
            const float* p1 = p0 + 64;  // (row + 8) * 8
            float s0 = 0.f, s1 = 0.f;
            #pragma unroll
            for (int t = 0; t < 8; ++t) { s0 += p0[t]; s1 += p1[t]; }
            inv0 = 1.f / s0;
            inv1 = 1.f / s1;
        }
        #pragma unroll
        for (int nt = 0; nt < NT; ++nt) {
            int col = n0 + wn * (BN_ / 4) + nt * 8 + tc * 2;
            float* a4 = acc[mt][nt];
            if constexpr (EPI == 3) {
                float* Cp = (float*)C + (size_t)bz * sC;
                float2 v0 = make_float2(a4[0], a4[1]);
                float2 v1 = make_float2(a4[2], a4[3]);
                const float* Rp = resid + (size_t)bz * sR;
                float2 x0 = *(const float2*)&Rp[(size_t)row * ldC + col];
                float2 x1 = *(const float2*)&Rp[(size_t)(row + 8) * ldC + col];
                v0.x += bv0 + x0.x; v0.y += bv0 + x0.y;
                v1.x += bv1 + x1.x; v1.y += bv1 + x1.y;
                *(float2*)&Cp[(size_t)row * ldC + col]       = v0;
                *(float2*)&Cp[(size_t)(row + 8) * ldC + col] = v1;
            } else if constexpr (EPI == 5) {
                bf16* Cp = (bf16*)C + (size_t)bz * sC;
                *(bf162*)&Cp[(size_t)row * ldC + col] =
                    __floats2bfloat162_rn(a4[0] * inv0, a4[1] * inv0);
                *(bf162*)&Cp[(size_t)(row + 8) * ldC + col] =
                    __floats2bfloat162_rn(a4[2] * inv1, a4[3] * inv1);
            } else {
                bf16* Cp = (bf16*)C + (size_t)bz * sC;
                *(bf162*)&Cp[(size_t)row * ldC + col] =
                    __floats2bfloat162_rn(a4[0] + bv0, a4[1] + bv0);
                *(bf162*)&Cp[(size_t)(row + 8) * ldC + col] =
                    __floats2bfloat162_rn(a4[2] + bv1, a4[3] + bv1);
            }
        }
    }
}

// ---------------- s_exp: E[n,m] = exp(scale * q.k), partial row sums ---------
static constexpr int TLD  = 136;
static constexpr int TSZ  = 64 * TLD;
static constexpr int TSMEM = 2 * 2 * TSZ * 2;

__global__ __launch_bounds__(256) void s_exp_kernel(
        const bf16* __restrict__ qkv, bf16* __restrict__ E, float* __restrict__ psum) {
    extern __shared__ bf16 tsm[];
    bf16* AsAll = tsm;
    bf16* BsAll = tsm + 2 * TSZ;
    __shared__ float rs[128][4];

    const int tid = threadIdx.x, lane = tid & 31, wid = tid >> 5;
    const int wm = wid & 1, wn = wid >> 1;
    const int m0 = blockIdx.y * 128, n0 = blockIdx.x * 128, bz = blockIdx.z;
    const bf16* qg = qkv + (size_t)bz * C3 * Nn;
    const bf16* kg = qg + (size_t)Cc * Nn;

    float acc[4][4][4];
    #pragma unroll
    for (int i = 0; i < 4; ++i)
        #pragma unroll
        for (int j = 0; j < 4; ++j)
            #pragma unroll
            for (int k = 0; k < 4; ++k) acc[i][j][k] = 0.f;

    const int lr = tid >> 4, lc = (tid & 15) * 8;

    auto load_stage = [&](int kt, int s) {
        bf16* As = AsAll + s * TSZ;
        bf16* Bs = BsAll + s * TSZ;
        #pragma unroll
        for (int i = 0; i < 4; ++i) {
            int r = lr + i * 16;
            cp_async16(smem_u32(As + r * TLD + lc),
                       qg + (size_t)(kt * 64 + r) * Nn + m0 + lc);
        }
        #pragma unroll
        for (int i = 0; i < 4; ++i) {
            int r = lr + i * 16;
            cp_async16(smem_u32(Bs + r * TLD + lc),
                       kg + (size_t)(kt * 64 + r) * Nn + n0 + lc);
        }
        cp_commit();
    };

    const int KT = Cc / 64;
    load_stage(0, 0);

    const int aRow = (lane & 7) + ((lane & 16) >> 1);
    const int aOff = ((lane >> 3) & 1) * 8;
    const int bRow = lane & 15;
    const int bOff = (lane >> 4) * 8;

    for (int kt = 0; kt < KT; ++kt) {
        if (kt + 1 < KT) {
            load_stage(kt + 1, (kt + 1) & 1);
            cp_wait<1>();
        } else {
            cp_wait<0>();
        }
        __syncthreads();

        const bf16* As = AsAll + (kt & 1) * TSZ;
        const bf16* Bs = BsAll + (kt & 1) * TSZ;
        uint32_t aBase = smem_u32(As + aRow * TLD + wm * 64 + aOff);
        uint32_t bBase = smem_u32(Bs + bRow * TLD + wn * 32 + bOff);

        #pragma unroll
        for (int ks = 0; ks < 4; ++ks) {
            uint32_t ar[4][4], br[2][4];
            #pragma unroll
            for (int mt = 0; mt < 4; ++mt)
                ldsm_x4_t(ar[mt], aBase + (uint32_t)(ks * 16 * TLD + mt * 16) * 2);
            #pragma unroll
            for (int rg = 0; rg < 2; ++rg)
                ldsm_x4_t(br[rg], bBase + (uint32_t)(ks * 16 * TLD + rg * 16) * 2);
            #pragma unroll
            for (int mt = 0; mt < 4; ++mt)
                #pragma unroll
                for (int rg = 0; rg < 2; ++rg) {
                    mma_16816(acc[mt][rg * 2],     ar[mt], br[rg][0], br[rg][1]);
                    mma_16816(acc[mt][rg * 2 + 1], ar[mt], br[rg][2], br[rg][3]);
                }
        }
        __syncthreads();
    }

    const float scl = 0.04419417382415922f;
    const int g = lane >> 2, tc = lane & 3;
    bf16* Eb = E + (size_t)bz * Nn * Nn;
    #pragma unroll
    for (int mt = 0; mt < 4; ++mt) {
        int rlocal = wm * 64 + mt * 16 + g;
        int row = m0 + rlocal;
        float rs_lo = 0.f, rs_hi = 0.f;
        #pragma unroll
        for (int nt = 0; nt < 4; ++nt) {
            float* a4 = acc[mt][nt];
            a4[0] = __expf(a4[0] * scl);
            a4[1] = __expf(a4[1] * scl);
            a4[2] = __expf(a4[2] * scl);
            a4[3] = __expf(a4[3] * scl);
            rs_lo += a4[0] + a4[1];
            rs_hi += a4[2] + a4[3];
            int col = n0 + wn * 32 + nt * 8 + tc * 2;
            *(bf162*)&Eb[(size_t)row * Nn + col] =
                __floats2bfloat162_rn(a4[0], a4[1]);
            *(bf162*)&Eb[(size_t)(row + 8) * Nn + col] =
                __floats2bfloat162_rn(a4[2], a4[3]);
        }
        rs_lo += __shfl_xor_sync(~0u, rs_lo, 1);
        rs_lo += __shfl_xor_sync(~0u, rs_lo, 2);
        rs_hi += __shfl_xor_sync(~0u, rs_hi, 1);
        rs_hi += __shfl_xor_sync(~0u, rs_hi, 2);
        if (tc == 0) {
            rs[rlocal][wn]     = rs_lo;
            rs[rlocal + 8][wn] = rs_hi;
        }
    }
    __syncthreads();
    if (tid < 128) {
        float s = rs[tid][0] + rs[tid][1] + rs[tid][2] + rs[tid][3];
        psum[((size_t)bz * Nn + m0 + tid) * 8 + blockIdx.x] = s;
    }
}

// ---------------- stage 1: weight convert ----------------
__global__ void wconv_kernel(const float* __restrict__ w1, const float* __restrict__ w2,
                             bf16* __restrict__ w1b, bf16* __restrict__ w2b) {
    int i = blockIdx.x * 256 + threadIdx.x;
    if (i < C3 * Cc) w1b[i] = __float2bfloat16(w1[i]);
    if (i < Cc * Cc) w2b[i] = __float2bfloat16(w2[i]);
}

// ---------------- stage 2: groupnorm stats ----------------
__global__ __launch_bounds__(256) void gn_stats_kernel(
        const float* __restrict__ x, const float* __restrict__ gns,
        const float* __restrict__ gnb, float* __restrict__ ga, float* __restrict__ gb) {
    int bg = blockIdx.x;
    const float4* p = reinterpret_cast<const float4*>(x) + (size_t)bg * 4096;
    float s = 0.f, ss = 0.f;
    for (int i = threadIdx.x; i < 4096; i += 256) {
        float4 v = p[i];
        s  += v.x + v.y + v.z + v.w;
        ss += v.x * v.x + v.y * v.y + v.z * v.z + v.w * v.w;
    }
    __shared__ float sh[34];
    #pragma unroll
    for (int o = 16; o > 0; o >>= 1) {
        s  += __shfl_xor_sync(~0u, s, o);
        ss += __shfl_xor_sync(~0u, ss, o);
    }
    int w = threadIdx.x >> 5;
    if ((threadIdx.x & 31) == 0) { sh[w] = s; sh[w + 8] = ss; }
    __syncthreads();
    if (threadIdx.x == 0) {
        float ts = 0.f, tss = 0.f;
        #pragma unroll
        for (int i = 0; i < 8; ++i) { ts += sh[i]; tss += sh[i + 8]; }
        sh[32] = ts; sh[33] = tss;
    }
    __syncthreads();
    float mean = sh[32] * (1.f / 16384.f);
    float var  = sh[33] * (1.f / 16384.f) - mean * mean;
    float rstd = rsqrtf(var + 1e-5f);
    if (threadIdx.x < 16) {
        int gI = bg & 31, c = gI * 16 + threadIdx.x;
        float sc = gns[c] * rstd;
        ga[(bg >> 5) * Cc + c] = sc;
        gb[(bg >> 5) * Cc + c] = gnb[c] - mean * sc;
    }
}

// ---------------- stage 3: normalize + transpose -> xnT[b][n][c] ----------------
__global__ void gn_apply_t_kernel(const float* __restrict__ x, const float* __restrict__ ga,
                                  const float* __restrict__ gb, bf16* __restrict__ xnT) {
    __shared__ float t[32][33];
    int b = blockIdx.z;
    const float* xb = x + (size_t)b * Cc * Nn;
    int n0 = blockIdx.x * 32, c0 = blockIdx.y * 32;
    #pragma unroll
    for (int j = 0; j < 4; ++j) {
        int c = c0 + threadIdx.y + 8 * j;
        float v = xb[(size_t)c * Nn + n0 + threadIdx.x];
        t[threadIdx.y + 8 * j][threadIdx.x] = v * ga[b * Cc + c] + gb[b * Cc + c];
    }
    __syncthreads();
    bf16* ob = xnT + (size_t)b * Nn * Cc;
    #pragma unroll
    for (int j = 0; j < 4; ++j) {
        int n = n0 + threadIdx.y + 8 * j;
        ob[(size_t)n * Cc + c0 + threadIdx.x] =
            __float2bfloat16(t[threadIdx.x][threadIdx.y + 8 * j]);
    }
}

// ---------------- host launcher (single stream) ----------------
extern "C" void kernel_launch(void* const* d_in, const int* in_sizes, int n_in,
                              void* d_out, int out_size) {
    (void)in_sizes; (void)n_in; (void)out_size;
    const float* x   = (const float*)d_in[0];
    const float* gns = (const float*)d_in[1];
    const float* gnb = (const float*)d_in[2];
    const float* w1  = (const float*)d_in[3];
    const float* b1  = (const float*)d_in[4];
    const float* w2  = (const float*)d_in[5];
    const float* b2  = (const float*)d_in[6];
    float* out = (float*)d_out;

    void *pga, *pgb, *pw1, *pw2, *pxn, *pqkv, *pE, *pps, *pattn;
    cudaGetSymbolAddress(&pga, g_ga);
    cudaGetSymbolAddress(&pgb, g_gb);
    cudaGetSymbolAddress(&pw1, g_w1b);
    cudaGetSymbolAddress(&pw2, g_w2b);
    cudaGetSymbolAddress(&pxn, g_xnT);
    cudaGetSymbolAddress(&pqkv, g_qkv);
    cudaGetSymbolAddress(&pE, g_E);
    cudaGetSymbolAddress(&pps, g_psum);
    cudaGetSymbolAddress(&pattn, g_attn);

    constexpr int SM128 = GCfg<128>::SMEM;  // 110592
    constexpr int SM64  = GCfg<64>::SMEM;   // 82944
    cudaFuncSetAttribute(gemm_bt<0, 128>, cudaFuncAttributeMaxDynamicSharedMemorySize, SM128);
    cudaFuncSetAttribute(gemm_bt<5, 64>,  cudaFuncAttributeMaxDynamicSharedMemorySize, SM64);
    cudaFuncSetAttribute(gemm_bt<3, 64>,  cudaFuncAttributeMaxDynamicSharedMemorySize, SM64);
    cudaFuncSetAttribute(s_exp_kernel, cudaFuncAttributeMaxDynamicSharedMemorySize, TSMEM);

    // 1) weights -> bf16
    wconv_kernel<<<3072, 256>>>(w1, w2, (bf16*)pw1, (bf16*)pw2);
    // 2) groupnorm stats
    gn_stats_kernel<<<Bb * 32, 256>>>(x, gns, gnb, (float*)pga, (float*)pgb);
    // 3) normalize + transpose -> xnT [b,n,c]
    gn_apply_t_kernel<<<dim3(32, 16, Bb), dim3(32, 8)>>>(x, (float*)pga, (float*)pgb,
                                                         (bf16*)pxn);
    // 4) QKV: qkv[o,n] = w1[o,:] . xnT[n,:] + b1[o]   (BN=128, as R9)
    gemm_bt<0, 128><<<dim3(8, 12, Bb), 256, SM128>>>(
        (const bf16*)pw1, (const bf16*)pxn, pqkv, b1, nullptr,
        C3, Nn, Cc, Cc, Cc, Nn, 0L, (long)Nn * Cc, (long)C3 * Nn, 0L);
    // 5) E = exp(scale * q^T k) + partial row sums
    s_exp_kernel<<<dim3(8, 8, Bb), 256, TSMEM>>>((const bf16*)pqkv, (bf16*)pE,
                                                 (float*)pps);
    // 6) attn[n,c] = (1/rowsum[n]) * E[n,:] . v[c,:]   (BN=64: 2048 CTAs, ~1% tail)
    gemm_bt<5, 64><<<dim3(8, 8, Bb), 256, SM64>>>(
        (const bf16*)pE, (const bf16*)pqkv + (size_t)2 * Cc * Nn, pattn,
        (const float*)pps, nullptr,
        Nn, Cc, Nn, Nn, Nn, Cc, (long)Nn * Nn, (long)C3 * Nn, (long)Nn * Cc, 0L);
    // 7) out[o,n] = w2[o,:] . attn[n,:] + b2[o] + x[o,n]   (BN=64: 2048 CTAs)
    gemm_bt<3, 64><<<dim3(16, 4, Bb), 256, SM64>>>(
        (const bf16*)pw2, (const bf16*)pattn, out, b2, x,
        Cc, Nn, Cc, Cc, Cc, Nn, 0L, (long)Nn * Cc, (long)Cc * Nn, (long)Cc * Nn);
}

// round 16
// speedup vs baseline: 1.0885x; 1.0885x over previous
#include <cuda_runtime.h>
#include <cuda_bf16.h>
#include <cstdint>

using bf16  = __nv_bfloat16;
using bf162 = __nv_bfloat162;

static constexpr int Bb = 32, Cc = 512, Nn = 1024, C3 = 1536;

// ---------------- device scratch ----------------
__device__ __align__(16) float g_ga[Bb * Cc];
__device__ __align__(16) float g_gb[Bb * Cc];
__device__ __align__(16) bf16  g_w1b[C3 * Cc];
__device__ __align__(16) bf16  g_w2b[Cc * Cc];
__device__ __align__(16) bf16  g_xnT [(size_t)Bb * Nn * Cc];
__device__ __align__(16) bf16  g_qkv [(size_t)Bb * C3 * Nn];
__device__ __align__(16) bf16  g_E   [(size_t)Bb * Nn * Nn];
__device__ __align__(16) float g_psum[(size_t)Bb * Nn * 8];
__device__ __align__(16) bf16  g_attn[(size_t)Bb * Nn * Cc];

// ---------------- PTX helpers ----------------
__device__ __forceinline__ uint32_t smem_u32(const void* p) {
    return (uint32_t)__cvta_generic_to_shared(p);
}
__device__ __forceinline__ void cp_async16(uint32_t s, const void* g) {
    asm volatile("cp.async.cg.shared.global [%0], [%1], 16;\n" :: "r"(s), "l"(g));
}
__device__ __forceinline__ void cp_commit() {
    asm volatile("cp.async.commit_group;\n" ::: "memory");
}
template <int N>
__device__ __forceinline__ void cp_wait() {
    asm volatile("cp.async.wait_group %0;\n" :: "n"(N) : "memory");
}
__device__ __forceinline__ void ldsm_x4(uint32_t* r, uint32_t addr) {
    asm volatile("ldmatrix.sync.aligned.m8n8.x4.shared.b16 {%0,%1,%2,%3}, [%4];\n"
                 : "=r"(r[0]), "=r"(r[1]), "=r"(r[2]), "=r"(r[3]) : "r"(addr));
}
__device__ __forceinline__ void ldsm_x4_t(uint32_t* r, uint32_t addr) {
    asm volatile("ldmatrix.sync.aligned.m8n8.x4.trans.shared.b16 {%0,%1,%2,%3}, [%4];\n"
                 : "=r"(r[0]), "=r"(r[1]), "=r"(r[2]), "=r"(r[3]) : "r"(addr));
}
__device__ __forceinline__ void mma_16816(float* d, const uint32_t* a,
                                          uint32_t b0, uint32_t b1) {
    asm volatile("mma.sync.aligned.m16n8k16.row.col.f32.bf16.bf16.f32 "
                 "{%0,%1,%2,%3}, {%4,%5,%6,%7}, {%8,%9}, {%0,%1,%2,%3};\n"
                 : "+f"(d[0]), "+f"(d[1]), "+f"(d[2]), "+f"(d[3])
                 : "r"(a[0]), "r"(a[1]), "r"(a[2]), "r"(a[3]), "r"(b0), "r"(b1));
}

// ---------------- bf16 GEMM: D[M,N] = A[M,K] @ B[N,K]^T (R4 config) ----------
// 128x128 tile, 256 threads, 2x4 warps (warp 64x32), BK=64, 3 stages.
// EPI: 0 = bf16 + bias[row], 3 = f32 + bias[row] + resid,
//      5 = bf16 scaled by 1/rowsum (bias = psum[b][row][8] partials)
static constexpr int BM = 128, BN = 128, BK = 64, PAD = 8, NST = 3;
static constexpr int LDT = BK + PAD;
static constexpr int SAe = BM * LDT;
static constexpr int GSMEM = 2 * NST * SAe * 2;

template <int EPI>
__global__ __launch_bounds__(256) void gemm_bt(
        const bf16* __restrict__ A, const bf16* __restrict__ B, void* __restrict__ C,
        const float* __restrict__ bias, const float* __restrict__ resid,
        int M, int N, int K, int ldA, int ldB, int ldC,
        long sA, long sB, long sC, long sR) {
    extern __shared__ bf16 sm[];
    bf16* AsAll = sm;
    bf16* BsAll = sm + NST * SAe;

    const int tid = threadIdx.x, lane = tid & 31, wid = tid >> 5;
    const int wm = wid & 1, wn = wid >> 1;
    const int m0 = blockIdx.y * BM, n0 = blockIdx.x * BN, bz = blockIdx.z;
    A += (size_t)bz * sA;
    B += (size_t)bz * sB;

    float acc[4][4][4];
    #pragma unroll
    for (int i = 0; i < 4; ++i)
        #pragma unroll
        for (int j = 0; j < 4; ++j)
            #pragma unroll
            for (int k = 0; k < 4; ++k) acc[i][j][k] = 0.f;

    const int lr = tid >> 3, lc = (tid & 7) * 8;

    auto load_stage = [&](int kt, int s) {
        bf16* As = AsAll + s * SAe;
        bf16* Bs = BsAll + s * SAe;
        const bf16* Ag = A + (size_t)m0 * ldA + kt * BK;
        const bf16* Bg = B + (size_t)n0 * ldB + kt * BK;
        #pragma unroll
        for (int i = 0; i < 4; ++i) {
            int r = lr + i * 32;
            cp_async16(smem_u32(As + r * LDT + lc), Ag + (size_t)r * ldA + lc);
        }
        #pragma unroll
        for (int i = 0; i < 4; ++i) {
            int r = lr + i * 32;
            cp_async16(smem_u32(Bs + r * LDT + lc), Bg + (size_t)r * ldB + lc);
        }
        cp_commit();
    };

    const int KT = K / BK;
    load_stage(0, 0);
    load_stage(1, 1);

    int sIdx = 0;
    for (int kt = 0; kt < KT; ++kt) {
        if (kt == KT - 1) cp_wait<0>(); else cp_wait<1>();
        __syncthreads();
        if (kt + 2 < KT) {
            int ns = sIdx + 2; if (ns >= NST) ns -= NST;
            load_stage(kt + 2, ns);
        }

        const bf16* As = AsAll + sIdx * SAe;
        const bf16* Bs = BsAll + sIdx * SAe;
        uint32_t aAddr = smem_u32(As + (wm * 64 + (lane & 15)) * LDT + (lane >> 4) * 8);
        uint32_t bAddr = smem_u32(Bs + (wn * 32 + (lane & 15)) * LDT + (lane >> 4) * 8);

        #pragma unroll
        for (int ks = 0; ks < 4; ++ks) {
            uint32_t ar[4][4], br[2][4];
            #pragma unroll
            for (int mt = 0; mt < 4; ++mt)
                ldsm_x4(ar[mt], aAddr + (uint32_t)(mt * 16 * LDT + ks * 16) * 2);
            #pragma unroll
            for (int rg = 0; rg < 2; ++rg)
                ldsm_x4(br[rg], bAddr + (uint32_t)(rg * 16 * LDT + ks * 16) * 2);
            #pragma unroll
            for (int mt = 0; mt < 4; ++mt)
                #pragma unroll
                for (int nt = 0; nt < 4; ++nt)
                    mma_16816(acc[mt][nt], ar[mt],
                              br[nt >> 1][nt & 1], br[nt >> 1][(nt & 1) + 2]);
        }
        ++sIdx; if (sIdx >= NST) sIdx = 0;
    }

    const int g = lane >> 2, tc = lane & 3;
    #pragma unroll
    for (int mt = 0; mt < 4; ++mt) {
        int row = m0 + wm * 64 + mt * 16 + g;
        float bv0 = 0.f, bv1 = 0.f;
        if constexpr (EPI == 0 || EPI == 3) { bv0 = bias[row]; bv1 = bias[row + 8]; }
        float inv0 = 1.f, inv1 = 1.f;
        if constexpr (EPI == 5) {
            const float* p0 = bias + ((size_t)bz * Nn + row) * 8;
            const float* p1 = p0 + 64;  // (row + 8) * 8
            float s0 = 0.f, s1 = 0.f;
            #pragma unroll
            for (int t = 0; t < 8; ++t) { s0 += p0[t]; s1 += p1[t]; }
            inv0 = 1.f / s0;
            inv1 = 1.f / s1;
        }
        #pragma unroll
        for (int nt = 0; nt < 4; ++nt) {
            int col = n0 + wn * 32 + nt * 8 + tc * 2;
            float* a4 = acc[mt][nt];
            if constexpr (EPI == 3) {
                float* Cp = (float*)C + (size_t)bz * sC;
                float2 v0 = make_float2(a4[0], a4[1]);
                float2 v1 = make_float2(a4[2], a4[3]);
                const float* Rp = resid + (size_t)bz * sR;
                float2 x0 = *(const float2*)&Rp[(size_t)row * ldC + col];
                float2 x1 = *(const float2*)&Rp[(size_t)(row + 8) * ldC + col];
                v0.x += bv0 + x0.x; v0.y += bv0 + x0.y;
                v1.x += bv1 + x1.x; v1.y += bv1 + x1.y;
                *(float2*)&Cp[(size_t)row * ldC + col]       = v0;
                *(float2*)&Cp[(size_t)(row + 8) * ldC + col] = v1;
            } else if constexpr (EPI == 5) {
                bf16* Cp = (bf16*)C + (size_t)bz * sC;
                *(bf162*)&Cp[(size_t)row * ldC + col] =
                    __floats2bfloat162_rn(a4[0] * inv0, a4[1] * inv0);
                *(bf162*)&Cp[(size_t)(row + 8) * ldC + col] =
                    __floats2bfloat162_rn(a4[2] * inv1, a4[3] * inv1);
            } else {
                bf16* Cp = (bf16*)C + (size_t)bz * sC;
                *(bf162*)&Cp[(size_t)row * ldC + col] =
                    __floats2bfloat162_rn(a4[0] + bv0, a4[1] + bv0);
                *(bf162*)&Cp[(size_t)(row + 8) * ldC + col] =
                    __floats2bfloat162_rn(a4[2] + bv1, a4[3] + bv1);
            }
        }
    }
}

// ---------------- s_exp: E[n,m] = exp(scale * q.k), partial row sums ---------
static constexpr int TLD  = 136;
static constexpr int TSZ  = 64 * TLD;
static constexpr int TSMEM = 2 * 2 * TSZ * 2;

__global__ __launch_bounds__(256) void s_exp_kernel(
        const bf16* __restrict__ qkv, bf16* __restrict__ E, float* __restrict__ psum) {
    extern __shared__ bf16 tsm[];
    bf16* AsAll = tsm;
    bf16* BsAll = tsm + 2 * TSZ;
    __shared__ float rs[128][4];

    const int tid = threadIdx.x, lane = tid & 31, wid = tid >> 5;
    const int wm = wid & 1, wn = wid >> 1;
    const int m0 = blockIdx.y * 128, n0 = blockIdx.x * 128, bz = blockIdx.z;
    const bf16* qg = qkv + (size_t)bz * C3 * Nn;
    const bf16* kg = qg + (size_t)Cc * Nn;

    float acc[4][4][4];
    #pragma unroll
    for (int i = 0; i < 4; ++i)
        #pragma unroll
        for (int j = 0; j < 4; ++j)
            #pragma unroll
            for (int k = 0; k < 4; ++k) acc[i][j][k] = 0.f;

    const int lr = tid >> 4, lc = (tid & 15) * 8;

    auto load_stage = [&](int kt, int s) {
        bf16* As = AsAll + s * TSZ;
        bf16* Bs = BsAll + s * TSZ;
        #pragma unroll
        for (int i = 0; i < 4; ++i) {
            int r = lr + i * 16;
            cp_async16(smem_u32(As + r * TLD + lc),
                       qg + (size_t)(kt * 64 + r) * Nn + m0 + lc);
        }
        #pragma unroll
        for (int i = 0; i < 4; ++i) {
            int r = lr + i * 16;
            cp_async16(smem_u32(Bs + r * TLD + lc),
                       kg + (size_t)(kt * 64 + r) * Nn + n0 + lc);
        }
        cp_commit();
    };

    const int KT = Cc / 64;
    load_stage(0, 0);

    const int aRow = (lane & 7) + ((lane & 16) >> 1);
    const int aOff = ((lane >> 3) & 1) * 8;
    const int bRow = lane & 15;
    const int bOff = (lane >> 4) * 8;

    for (int kt = 0; kt < KT; ++kt) {
        if (kt + 1 < KT) {
            load_stage(kt + 1, (kt + 1) & 1);
            cp_wait<1>();
        } else {
            cp_wait<0>();
        }
        __syncthreads();

        const bf16* As = AsAll + (kt & 1) * TSZ;
        const bf16* Bs = BsAll + (kt & 1) * TSZ;
        uint32_t aBase = smem_u32(As + aRow * TLD + wm * 64 + aOff);
        uint32_t bBase = smem_u32(Bs + bRow * TLD + wn * 32 + bOff);

        #pragma unroll
        for (int ks = 0; ks < 4; ++ks) {
            uint32_t ar[4][4], br[2][4];
            #pragma unroll
            for (int mt = 0; mt < 4; ++mt)
                ldsm_x4_t(ar[mt], aBase + (uint32_t)(ks * 16 * TLD + mt * 16) * 2);
            #pragma unroll
            for (int rg = 0; rg < 2; ++rg)
                ldsm_x4_t(br[rg], bBase + (uint32_t)(ks * 16 * TLD + rg * 16) * 2);
            #pragma unroll
            for (int mt = 0; mt < 4; ++mt)
                #pragma unroll
                for (int rg = 0; rg < 2; ++rg) {
                    mma_16816(acc[mt][rg * 2],     ar[mt], br[rg][0], br[rg][1]);
                    mma_16816(acc[mt][rg * 2 + 1], ar[mt], br[rg][2], br[rg][3]);
                }
        }
        __syncthreads();
    }

    const float scl = 0.04419417382415922f;
    const int g = lane >> 2, tc = lane & 3;
    bf16* Eb = E + (size_t)bz * Nn * Nn;
    #pragma unroll
    for (int mt = 0; mt < 4; ++mt) {
        int rlocal = wm * 64 + mt * 16 + g;
        int row = m0 + rlocal;
        float rs_lo = 0.f, rs_hi = 0.f;
        #pragma unroll
        for (int nt = 0; nt < 4; ++nt) {
            float* a4 = acc[mt][nt];
            a4[0] = __expf(a4[0] * scl);
            a4[1] = __expf(a4[1] * scl);
            a4[2] = __expf(a4[2] * scl);
            a4[3] = __expf(a4[3] * scl);
            rs_lo += a4[0] + a4[1];
            rs_hi += a4[2] + a4[3];
            int col = n0 + wn * 32 + nt * 8 + tc * 2;
            *(bf162*)&Eb[(size_t)row * Nn + col] =
                __floats2bfloat162_rn(a4[0], a4[1]);
            *(bf162*)&Eb[(size_t)(row + 8) * Nn + col] =
                __floats2bfloat162_rn(a4[2], a4[3]);
        }
        rs_lo += __shfl_xor_sync(~0u, rs_lo, 1);
        rs_lo += __shfl_xor_sync(~0u, rs_lo, 2);
        rs_hi += __shfl_xor_sync(~0u, rs_hi, 1);
        rs_hi += __shfl_xor_sync(~0u, rs_hi, 2);
        if (tc == 0) {
            rs[rlocal][wn]     = rs_lo;
            rs[rlocal + 8][wn] = rs_hi;
        }
    }
    __syncthreads();
    if (tid < 128) {
        float s = rs[tid][0] + rs[tid][1] + rs[tid][2] + rs[tid][3];
        psum[((size_t)bz * Nn + m0 + tid) * 8 + blockIdx.x] = s;
    }
}

// ---------------- stage 1: weight convert ----------------
__global__ void wconv_kernel(const float* __restrict__ w1, const float* __restrict__ w2,
                             bf16* __restrict__ w1b, bf16* __restrict__ w2b) {
    int i = blockIdx.x * 256 + threadIdx.x;
    if (i < C3 * Cc) w1b[i] = __float2bfloat16(w1[i]);
    if (i < Cc * Cc) w2b[i] = __float2bfloat16(w2[i]);
}

// ---------------- stage 2: groupnorm stats ----------------
__global__ __launch_bounds__(256) void gn_stats_kernel(
        const float* __restrict__ x, const float* __restrict__ gns,
        const float* __restrict__ gnb, float* __restrict__ ga, float* __restrict__ gb) {
    int bg = blockIdx.x;
    const float4* p = reinterpret_cast<const float4*>(x) + (size_t)bg * 4096;
    float s = 0.f, ss = 0.f;
    for (int i = threadIdx.x; i < 4096; i += 256) {
        float4 v = p[i];
        s  += v.x + v.y + v.z + v.w;
        ss += v.x * v.x + v.y * v.y + v.z * v.z + v.w * v.w;
    }
    __shared__ float sh[34];
    #pragma unroll
    for (int o = 16; o > 0; o >>= 1) {
        s  += __shfl_xor_sync(~0u, s, o);
        ss += __shfl_xor_sync(~0u, ss, o);
    }
    int w = threadIdx.x >> 5;
    if ((threadIdx.x & 31) == 0) { sh[w] = s; sh[w + 8] = ss; }
    __syncthreads();
    if (threadIdx.x == 0) {
        float ts = 0.f, tss = 0.f;
        #pragma unroll
        for (int i = 0; i < 8; ++i) { ts += sh[i]; tss += sh[i + 8]; }
        sh[32] = ts; sh[33] = tss;
    }
    __syncthreads();
    float mean = sh[32] * (1.f / 16384.f);
    float var  = sh[33] * (1.f / 16384.f) - mean * mean;
    float rstd = rsqrtf(var + 1e-5f);
    if (threadIdx.x < 16) {
        int gI = bg & 31, c = gI * 16 + threadIdx.x;
        float sc = gns[c] * rstd;
        ga[(bg >> 5) * Cc + c] = sc;
        gb[(bg >> 5) * Cc + c] = gnb[c] - mean * sc;
    }
}

// ---------------- stage 3: normalize + transpose -> xnT[b][n][c] ----------------
__global__ void gn_apply_t_kernel(const float* __restrict__ x, const float* __restrict__ ga,
                                  const float* __restrict__ gb, bf16* __restrict__ xnT) {
    __shared__ float t[32][33];
    int b = blockIdx.z;
    const float* xb = x + (size_t)b * Cc * Nn;
    int n0 = blockIdx.x * 32, c0 = blockIdx.y * 32;
    #pragma unroll
    for (int j = 0; j < 4; ++j) {
        int c = c0 + threadIdx.y + 8 * j;
        float v = xb[(size_t)c * Nn + n0 + threadIdx.x];
        t[threadIdx.y + 8 * j][threadIdx.x] = v * ga[b * Cc + c] + gb[b * Cc + c];
    }
    __syncthreads();
    bf16* ob = xnT + (size_t)b * Nn * Cc;
    #pragma unroll
    for (int j = 0; j < 4; ++j) {
        int n = n0 + threadIdx.y + 8 * j;
        ob[(size_t)n * Cc + c0 + threadIdx.x] =
            __float2bfloat16(t[threadIdx.x][threadIdx.y + 8 * j]);
    }
}

// ---------------- host launcher (single stream, R9 configuration) ------------
extern "C" void kernel_launch(void* const* d_in, const int* in_sizes, int n_in,
                              void* d_out, int out_size) {
    (void)in_sizes; (void)n_in; (void)out_size;
    const float* x   = (const float*)d_in[0];
    const float* gns = (const float*)d_in[1];
    const float* gnb = (const float*)d_in[2];
    const float* w1  = (const float*)d_in[3];
    const float* b1  = (const float*)d_in[4];
    const float* w2  = (const float*)d_in[5];
    const float* b2  = (const float*)d_in[6];
    float* out = (float*)d_out;

    void *pga, *pgb, *pw1, *pw2, *pxn, *pqkv, *pE, *pps, *pattn;
    cudaGetSymbolAddress(&pga, g_ga);
    cudaGetSymbolAddress(&pgb, g_gb);
    cudaGetSymbolAddress(&pw1, g_w1b);
    cudaGetSymbolAddress(&pw2, g_w2b);
    cudaGetSymbolAddress(&pxn, g_xnT);
    cudaGetSymbolAddress(&pqkv, g_qkv);
    cudaGetSymbolAddress(&pE, g_E);
    cudaGetSymbolAddress(&pps, g_psum);
    cudaGetSymbolAddress(&pattn, g_attn);

    cudaFuncSetAttribute(gemm_bt<0>, cudaFuncAttributeMaxDynamicSharedMemorySize, GSMEM);
    cudaFuncSetAttribute(gemm_bt<3>, cudaFuncAttributeMaxDynamicSharedMemorySize, GSMEM);
    cudaFuncSetAttribute(gemm_bt<5>, cudaFuncAttributeMaxDynamicSharedMemorySize, GSMEM);
    cudaFuncSetAttribute(s_exp_kernel, cudaFuncAttributeMaxDynamicSharedMemorySize, TSMEM);

    // 1) weights -> bf16
    wconv_kernel<<<3072, 256>>>(w1, w2, (bf16*)pw1, (bf16*)pw2);
    // 2) groupnorm stats
    gn_stats_kernel<<<Bb * 32, 256>>>(x, gns, gnb, (float*)pga, (float*)pgb);
    // 3) normalize + transpose -> xnT [b,n,c]
    gn_apply_t_kernel<<<dim3(32, 16, Bb), dim3(32, 8)>>>(x, (float*)pga, (float*)pgb,
                                                         (bf16*)pxn);
    // 4) QKV: qkv[o,n] = w1[o,:] . xnT[n,:] + b1[o]
    gemm_bt<0><<<dim3(8, 12, Bb), 256, GSMEM>>>(
        (const bf16*)pw1, (const bf16*)pxn, pqkv, b1, nullptr,
        C3, Nn, Cc, Cc, Cc, Nn, 0L, (long)Nn * Cc, (long)C3 * Nn, 0L);
    // 5) E = exp(scale * q^T k) + partial row sums
    s_exp_kernel<<<dim3(8, 8, Bb), 256, TSMEM>>>((const bf16*)pqkv, (bf16*)pE,
                                                 (float*)pps);
    // 6) attn[n,c] = (1/rowsum[n]) * E[n,:] . v[c,:]
    gemm_bt<5><<<dim3(4, 8, Bb), 256, GSMEM>>>(
        (const bf16*)pE, (const bf16*)pqkv + (size_t)2 * Cc * Nn, pattn,
        (const float*)pps, nullptr,
        Nn, Cc, Nn, Nn, Nn, Cc, (long)Nn * Nn, (long)C3 * Nn, (long)Nn * Cc, 0L);
    // 7) out[o,n] = w2[o,:] . attn[n,:] + b2[o] + x[o,n]  (fused residual)
    gemm_bt<3><<<dim3(8, 4, Bb), 256, GSMEM>>>(
        (const bf16*)pw2, (const bf16*)pattn, out, b2, x,
        Cc, Nn, Cc, Cc, Cc, Nn, 0L, (long)Nn * Cc, (long)Cc * Nn, (long)Cc * Nn);
}

// round 17
// speedup vs baseline: 1.1288x; 1.0370x over previous
#include <cuda_runtime.h>
#include <cuda_bf16.h>
#include <cstdint>

using bf16  = __nv_bfloat16;
using bf162 = __nv_bfloat162;

static constexpr int Bb = 32, Cc = 512, Nn = 1024, C3 = 1536;

// ---------------- device scratch ----------------
__device__ __align__(16) float g_ga[Bb * Cc];
__device__ __align__(16) float g_gb[Bb * Cc];
__device__ __align__(16) bf16  g_w1b[C3 * Cc];
__device__ __align__(16) bf16  g_w2b[Cc * Cc];
__device__ __align__(16) bf16  g_xnT [(size_t)Bb * Nn * Cc];
__device__ __align__(16) bf16  g_qkv [(size_t)Bb * C3 * Nn];
__device__ __align__(16) bf16  g_E   [(size_t)Bb * Nn * Nn];
__device__ __align__(16) float g_psum[(size_t)Bb * Nn * 8];
__device__ __align__(16) bf16  g_attn[(size_t)Bb * Nn * Cc];

// ---------------- PTX helpers ----------------
__device__ __forceinline__ uint32_t smem_u32(const void* p) {
    return (uint32_t)__cvta_generic_to_shared(p);
}
__device__ __forceinline__ void cp_async16(uint32_t s, const void* g) {
    asm volatile("cp.async.cg.shared.global [%0], [%1], 16;\n" :: "r"(s), "l"(g));
}
__device__ __forceinline__ void cp_commit() {
    asm volatile("cp.async.commit_group;\n" ::: "memory");
}
template <int N>
__device__ __forceinline__ void cp_wait() {
    asm volatile("cp.async.wait_group %0;\n" :: "n"(N) : "memory");
}
__device__ __forceinline__ void ldsm_x4(uint32_t* r, uint32_t addr) {
    asm volatile("ldmatrix.sync.aligned.m8n8.x4.shared.b16 {%0,%1,%2,%3}, [%4];\n"
                 : "=r"(r[0]), "=r"(r[1]), "=r"(r[2]), "=r"(r[3]) : "r"(addr));
}
__device__ __forceinline__ void ldsm_x4_t(uint32_t* r, uint32_t addr) {
    asm volatile("ldmatrix.sync.aligned.m8n8.x4.trans.shared.b16 {%0,%1,%2,%3}, [%4];\n"
                 : "=r"(r[0]), "=r"(r[1]), "=r"(r[2]), "=r"(r[3]) : "r"(addr));
}
__device__ __forceinline__ void mma_16816(float* d, const uint32_t* a,
                                          uint32_t b0, uint32_t b1) {
    asm volatile("mma.sync.aligned.m16n8k16.row.col.f32.bf16.bf16.f32 "
                 "{%0,%1,%2,%3}, {%4,%5,%6,%7}, {%8,%9}, {%0,%1,%2,%3};\n"
                 : "+f"(d[0]), "+f"(d[1]), "+f"(d[2]), "+f"(d[3])
                 : "r"(a[0]), "r"(a[1]), "r"(a[2]), "r"(a[3]), "r"(b0), "r"(b1));
}

// ---------------- bf16 GEMM: D[M,N] = A[M,K] @ B[N,K]^T (R4 config) ----------
// 128x128 tile, 256 threads, 2x4 warps (warp 64x32), BK=64, 3 stages.
// EPI: 0 = bf16 + bias[row], 3 = f32 + bias[row] + resid,
//      5 = bf16 scaled by 1/rowsum (bias = psum[b][row][8] partials)
static constexpr int BM = 128, BN = 128, BK = 64, PAD = 8, NST = 3;
static constexpr int LDT = BK + PAD;
static constexpr int SAe = BM * LDT;
static constexpr int GSMEM = 2 * NST * SAe * 2;

template <int EPI>
__global__ __launch_bounds__(256) void gemm_bt(
        const bf16* __restrict__ A, const bf16* __restrict__ B, void* __restrict__ C,
        const float* __restrict__ bias, const float* __restrict__ resid,
        int M, int N, int K, int ldA, int ldB, int ldC,
        long sA, long sB, long sC, long sR) {
    extern __shared__ bf16 sm[];
    bf16* AsAll = sm;
    bf16* BsAll = sm + NST * SAe;

    const int tid = threadIdx.x, lane = tid & 31, wid = tid >> 5;
    const int wm = wid & 1, wn = wid >> 1;
    const int m0 = blockIdx.y * BM, n0 = blockIdx.x * BN, bz = blockIdx.z;
    A += (size_t)bz * sA;
    B += (size_t)bz * sB;

    float acc[4][4][4];
    #pragma unroll
    for (int i = 0; i < 4; ++i)
        #pragma unroll
        for (int j = 0; j < 4; ++j)
            #pragma unroll
            for (int k = 0; k < 4; ++k) acc[i][j][k] = 0.f;

    const int lr = tid >> 3, lc = (tid & 7) * 8;

    auto load_stage = [&](int kt, int s) {
        bf16* As = AsAll + s * SAe;
        bf16* Bs = BsAll + s * SAe;
        const bf16* Ag = A + (size_t)m0 * ldA + kt * BK;
        const bf16* Bg = B + (size_t)n0 * ldB + kt * BK;
        #pragma unroll
        for (int i = 0; i < 4; ++i) {
            int r = lr + i * 32;
            cp_async16(smem_u32(As + r * LDT + lc), Ag + (size_t)r * ldA + lc);
        }
        #pragma unroll
        for (int i = 0; i < 4; ++i) {
            int r = lr + i * 32;
            cp_async16(smem_u32(Bs + r * LDT + lc), Bg + (size_t)r * ldB + lc);
        }
        cp_commit();
    };

    const int KT = K / BK;
    load_stage(0, 0);
    load_stage(1, 1);

    int sIdx = 0;
    for (int kt = 0; kt < KT; ++kt) {
        if (kt == KT - 1) cp_wait<0>(); else cp_wait<1>();
        __syncthreads();
        if (kt + 2 < KT) {
            int ns = sIdx + 2; if (ns >= NST) ns -= NST;
            load_stage(kt + 2, ns);
        }

        const bf16* As = AsAll + sIdx * SAe;
        const bf16* Bs = BsAll + sIdx * SAe;
        uint32_t aAddr = smem_u32(As + (wm * 64 + (lane & 15)) * LDT + (lane >> 4) * 8);
        uint32_t bAddr = smem_u32(Bs + (wn * 32 + (lane & 15)) * LDT + (lane >> 4) * 8);

        #pragma unroll
        for (int ks = 0; ks < 4; ++ks) {
            uint32_t ar[4][4], br[2][4];
            #pragma unroll
            for (int mt = 0; mt < 4; ++mt)
                ldsm_x4(ar[mt], aAddr + (uint32_t)(mt * 16 * LDT + ks * 16) * 2);
            #pragma unroll
            for (int rg = 0; rg < 2; ++rg)
                ldsm_x4(br[rg], bAddr + (uint32_t)(rg * 16 * LDT + ks * 16) * 2);
            #pragma unroll
            for (int mt = 0; mt < 4; ++mt)
                #pragma unroll
                for (int nt = 0; nt < 4; ++nt)
                    mma_16816(acc[mt][nt], ar[mt],
                              br[nt >> 1][nt & 1], br[nt >> 1][(nt & 1) + 2]);
        }
        ++sIdx; if (sIdx >= NST) sIdx = 0;
    }

    const int g = lane >> 2, tc = lane & 3;
    #pragma unroll
    for (int mt = 0; mt < 4; ++mt) {
        int row = m0 + wm * 64 + mt * 16 + g;
        float bv0 = 0.f, bv1 = 0.f;
        if constexpr (EPI == 0 || EPI == 3) { bv0 = bias[row]; bv1 = bias[row + 8]; }
        float inv0 = 1.f, inv1 = 1.f;
        if constexpr (EPI == 5) {
            const float* p0 = bias + ((size_t)bz * Nn + row) * 8;
            const float* p1 = p0 + 64;  // (row + 8) * 8
            float s0 = 0.f, s1 = 0.f;
            #pragma unroll
            for (int t = 0; t < 8; ++t) { s0 += p0[t]; s1 += p1[t]; }
            inv0 = 1.f / s0;
            inv1 = 1.f / s1;
        }
        #pragma unroll
        for (int nt = 0; nt < 4; ++nt) {
            int col = n0 + wn * 32 + nt * 8 + tc * 2;
            float* a4 = acc[mt][nt];
            if constexpr (EPI == 3) {
                float* Cp = (float*)C + (size_t)bz * sC;
                float2 v0 = make_float2(a4[0], a4[1]);
                float2 v1 = make_float2(a4[2], a4[3]);
                const float* Rp = resid + (size_t)bz * sR;
                float2 x0 = *(const float2*)&Rp[(size_t)row * ldC + col];
                float2 x1 = *(const float2*)&Rp[(size_t)(row + 8) * ldC + col];
                v0.x += bv0 + x0.x; v0.y += bv0 + x0.y;
                v1.x += bv1 + x1.x; v1.y += bv1 + x1.y;
                *(float2*)&Cp[(size_t)row * ldC + col]       = v0;
                *(float2*)&Cp[(size_t)(row + 8) * ldC + col] = v1;
            } else if constexpr (EPI == 5) {
                bf16* Cp = (bf16*)C + (size_t)bz * sC;
                *(bf162*)&Cp[(size_t)row * ldC + col] =
                    __floats2bfloat162_rn(a4[0] * inv0, a4[1] * inv0);
                *(bf162*)&Cp[(size_t)(row + 8) * ldC + col] =
                    __floats2bfloat162_rn(a4[2] * inv1, a4[3] * inv1);
            } else {
                bf16* Cp = (bf16*)C + (size_t)bz * sC;
                *(bf162*)&Cp[(size_t)row * ldC + col] =
                    __floats2bfloat162_rn(a4[0] + bv0, a4[1] + bv0);
                *(bf162*)&Cp[(size_t)(row + 8) * ldC + col] =
                    __floats2bfloat162_rn(a4[2] + bv1, a4[3] + bv1);
            }
        }
    }
}

// ---------------- s_exp: E[n,m] = exp(scale * q.k), partial row sums ---------
static constexpr int TLD  = 136;
static constexpr int TSZ  = 64 * TLD;
static constexpr int TSMEM = 2 * 2 * TSZ * 2;

__global__ __launch_bounds__(256) void s_exp_kernel(
        const bf16* __restrict__ qkv, bf16* __restrict__ E, float* __restrict__ psum) {
    extern __shared__ bf16 tsm[];
    bf16* AsAll = tsm;
    bf16* BsAll = tsm + 2 * TSZ;
    __shared__ float rs[128][4];

    const int tid = threadIdx.x, lane = tid & 31, wid = tid >> 5;
    const int wm = wid & 1, wn = wid >> 1;
    const int m0 = blockIdx.y * 128, n0 = blockIdx.x * 128, bz = blockIdx.z;
    const bf16* qg = qkv + (size_t)bz * C3 * Nn;
    const bf16* kg = qg + (size_t)Cc * Nn;

    float acc[4][4][4];
    #pragma unroll
    for (int i = 0; i < 4; ++i)
        #pragma unroll
        for (int j = 0; j < 4; ++j)
            #pragma unroll
            for (int k = 0; k < 4; ++k) acc[i][j][k] = 0.f;

    const int lr = tid >> 4, lc = (tid & 15) * 8;

    auto load_stage = [&](int kt, int s) {
        bf16* As = AsAll + s * TSZ;
        bf16* Bs = BsAll + s * TSZ;
        #pragma unroll
        for (int i = 0; i < 4; ++i) {
            int r = lr + i * 16;
            cp_async16(smem_u32(As + r * TLD + lc),
                       qg + (size_t)(kt * 64 + r) * Nn + m0 + lc);
        }
        #pragma unroll
        for (int i = 0; i < 4; ++i) {
            int r = lr + i * 16;
            cp_async16(smem_u32(Bs + r * TLD + lc),
                       kg + (size_t)(kt * 64 + r) * Nn + n0 + lc);
        }
        cp_commit();
    };

    const int KT = Cc / 64;
    load_stage(0, 0);

    const int aRow = (lane & 7) + ((lane & 16) >> 1);
    const int aOff = ((lane >> 3) & 1) * 8;
    const int bRow = lane & 15;
    const int bOff = (lane >> 4) * 8;

    for (int kt = 0; kt < KT; ++kt) {
        if (kt + 1 < KT) {
            load_stage(kt + 1, (kt + 1) & 1);
            cp_wait<1>();
        } else {
            cp_wait<0>();
        }
        __syncthreads();

        const bf16* As = AsAll + (kt & 1) * TSZ;
        const bf16* Bs = BsAll + (kt & 1) * TSZ;
        uint32_t aBase = smem_u32(As + aRow * TLD + wm * 64 + aOff);
        uint32_t bBase = smem_u32(Bs + bRow * TLD + wn * 32 + bOff);

        #pragma unroll
        for (int ks = 0; ks < 4; ++ks) {
            uint32_t ar[4][4], br[2][4];
            #pragma unroll
            for (int mt = 0; mt < 4; ++mt)
                ldsm_x4_t(ar[mt], aBase + (uint32_t)(ks * 16 * TLD + mt * 16) * 2);
            #pragma unroll
            for (int rg = 0; rg < 2; ++rg)
                ldsm_x4_t(br[rg], bBase + (uint32_t)(ks * 16 * TLD + rg * 16) * 2);
            #pragma unroll
            for (int mt = 0; mt < 4; ++mt)
                #pragma unroll
                for (int rg = 0; rg < 2; ++rg) {
                    mma_16816(acc[mt][rg * 2],     ar[mt], br[rg][0], br[rg][1]);
                    mma_16816(acc[mt][rg * 2 + 1], ar[mt], br[rg][2], br[rg][3]);
                }
        }
        __syncthreads();
    }

    const float scl = 0.04419417382415922f;
    const int g = lane >> 2, tc = lane & 3;
    bf16* Eb = E + (size_t)bz * Nn * Nn;
    #pragma unroll
    for (int mt = 0; mt < 4; ++mt) {
        int rlocal = wm * 64 + mt * 16 + g;
        int row = m0 + rlocal;
        float rs_lo = 0.f, rs_hi = 0.f;
        #pragma unroll
        for (int nt = 0; nt < 4; ++nt) {
            float* a4 = acc[mt][nt];
            a4[0] = __expf(a4[0] * scl);
            a4[1] = __expf(a4[1] * scl);
            a4[2] = __expf(a4[2] * scl);
            a4[3] = __expf(a4[3] * scl);
            rs_lo += a4[0] + a4[1];
            rs_hi += a4[2] + a4[3];
            int col = n0 + wn * 32 + nt * 8 + tc * 2;
            *(bf162*)&Eb[(size_t)row * Nn + col] =
                __floats2bfloat162_rn(a4[0], a4[1]);
            *(bf162*)&Eb[(size_t)(row + 8) * Nn + col] =
                __floats2bfloat162_rn(a4[2], a4[3]);
        }
        rs_lo += __shfl_xor_sync(~0u, rs_lo, 1);
        rs_lo += __shfl_xor_sync(~0u, rs_lo, 2);
        rs_hi += __shfl_xor_sync(~0u, rs_hi, 1);
        rs_hi += __shfl_xor_sync(~0u, rs_hi, 2);
        if (tc == 0) {
            rs[rlocal][wn]     = rs_lo;
            rs[rlocal + 8][wn] = rs_hi;
        }
    }
    __syncthreads();
    if (tid < 128) {
        float s = rs[tid][0] + rs[tid][1] + rs[tid][2] + rs[tid][3];
        psum[((size_t)bz * Nn + m0 + tid) * 8 + blockIdx.x] = s;
    }
}

// ---------------- stage 1: weight convert ----------------
__global__ void wconv_kernel(const float* __restrict__ w1, const float* __restrict__ w2,
                             bf16* __restrict__ w1b, bf16* __restrict__ w2b) {
    int i = blockIdx.x * 256 + threadIdx.x;
    if (i < C3 * Cc) w1b[i] = __float2bfloat16(w1[i]);
    if (i < Cc * Cc) w2b[i] = __float2bfloat16(w2[i]);
}

// ---------------- stage 2: groupnorm stats ----------------
__global__ __launch_bounds__(256) void gn_stats_kernel(
        const float* __restrict__ x, const float* __restrict__ gns,
        const float* __restrict__ gnb, float* __restrict__ ga, float* __restrict__ gb) {
    int bg = blockIdx.x;
    const float4* p = reinterpret_cast<const float4*>(x) + (size_t)bg * 4096;
    float s = 0.f, ss = 0.f;
    for (int i = threadIdx.x; i < 4096; i += 256) {
        float4 v = p[i];
        s  += v.x + v.y + v.z + v.w;
        ss += v.x * v.x + v.y * v.y + v.z * v.z + v.w * v.w;
    }
    __shared__ float sh[34];
    #pragma unroll
    for (int o = 16; o > 0; o >>= 1) {
        s  += __shfl_xor_sync(~0u, s, o);
        ss += __shfl_xor_sync(~0u, ss, o);
    }
    int w = threadIdx.x >> 5;
    if ((threadIdx.x & 31) == 0) { sh[w] = s; sh[w + 8] = ss; }
    __syncthreads();
    if (threadIdx.x == 0) {
        float ts = 0.f, tss = 0.f;
        #pragma unroll
        for (int i = 0; i < 8; ++i) { ts += sh[i]; tss += sh[i + 8]; }
        sh[32] = ts; sh[33] = tss;
    }
    __syncthreads();
    float mean = sh[32] * (1.f / 16384.f);
    float var  = sh[33] * (1.f / 16384.f) - mean * mean;
    float rstd = rsqrtf(var + 1e-5f);
    if (threadIdx.x < 16) {
        int gI = bg & 31, c = gI * 16 + threadIdx.x;
        float sc = gns[c] * rstd;
        ga[(bg >> 5) * Cc + c] = sc;
        gb[(bg >> 5) * Cc + c] = gnb[c] - mean * sc;
    }
}

// ---------------- stage 3: normalize + transpose -> xnT[b][n][c] ----------------
__global__ void gn_apply_t_kernel(const float* __restrict__ x, const float* __restrict__ ga,
                                  const float* __restrict__ gb, bf16* __restrict__ xnT) {
    __shared__ float t[32][33];
    int b = blockIdx.z;
    const float* xb = x + (size_t)b * Cc * Nn;
    int n0 = blockIdx.x * 32, c0 = blockIdx.y * 32;
    #pragma unroll
    for (int j = 0; j < 4; ++j) {
        int c = c0 + threadIdx.y + 8 * j;
        float v = xb[(size_t)c * Nn + n0 + threadIdx.x];
        t[threadIdx.y + 8 * j][threadIdx.x] = v * ga[b * Cc + c] + gb[b * Cc + c];
    }
    __syncthreads();
    bf16* ob = xnT + (size_t)b * Nn * Cc;
    #pragma unroll
    for (int j = 0; j < 4; ++j) {
        int n = n0 + threadIdx.y + 8 * j;
        ob[(size_t)n * Cc + c0 + threadIdx.x] =
            __float2bfloat16(t[threadIdx.x][threadIdx.y + 8 * j]);
    }
}

// ---------------- host launcher: two-stream batch-split pipeline ----------------
extern "C" void kernel_launch(void* const* d_in, const int* in_sizes, int n_in,
                              void* d_out, int out_size) {
    (void)in_sizes; (void)n_in; (void)out_size;
    const float* x   = (const float*)d_in[0];
    const float* gns = (const float*)d_in[1];
    const float* gnb = (const float*)d_in[2];
    const float* w1  = (const float*)d_in[3];
    const float* b1  = (const float*)d_in[4];
    const float* w2  = (const float*)d_in[5];
    const float* b2  = (const float*)d_in[6];
    float* out = (float*)d_out;

    void *pga, *pgb, *pw1, *pw2, *pxn, *pqkv, *pE, *pps, *pattn;
    cudaGetSymbolAddress(&pga, g_ga);
    cudaGetSymbolAddress(&pgb, g_gb);
    cudaGetSymbolAddress(&pw1, g_w1b);
    cudaGetSymbolAddress(&pw2, g_w2b);
    cudaGetSymbolAddress(&pxn, g_xnT);
    cudaGetSymbolAddress(&pqkv, g_qkv);
    cudaGetSymbolAddress(&pE, g_E);
    cudaGetSymbolAddress(&pps, g_psum);
    cudaGetSymbolAddress(&pattn, g_attn);

    cudaFuncSetAttribute(gemm_bt<0>, cudaFuncAttributeMaxDynamicSharedMemorySize, GSMEM);
    cudaFuncSetAttribute(gemm_bt<3>, cudaFuncAttributeMaxDynamicSharedMemorySize, GSMEM);
    cudaFuncSetAttribute(gemm_bt<5>, cudaFuncAttributeMaxDynamicSharedMemorySize, GSMEM);
    cudaFuncSetAttribute(s_exp_kernel, cudaFuncAttributeMaxDynamicSharedMemorySize, TSMEM);

    // lazy one-time stream/event setup (first call = uncaptured correctness run,
    // so the captured graph sees identical, pre-existing streams every capture)
    static cudaStream_t s2 = nullptr;
    static cudaEvent_t evF = nullptr, evJ = nullptr;
    if (s2 == nullptr) {
        cudaStreamCreateWithFlags(&s2, cudaStreamNonBlocking);
        cudaEventCreateWithFlags(&evF, cudaEventDisableTiming);
        cudaEventCreateWithFlags(&evJ, cudaEventDisableTiming);
    }

    // weights conversion (shared by both halves) on the main stream, then fork
    wconv_kernel<<<3072, 256, 0, 0>>>(w1, w2, (bf16*)pw1, (bf16*)pw2);
    cudaEventRecord(evF, 0);
    cudaStreamWaitEvent(s2, evF, 0);

    const int HB = Bb / 2;  // 16 batches per half
    for (int h = 0; h < 2; ++h) {
        cudaStream_t st = (h == 0) ? 0 : s2;
        size_t bo = (size_t)h * HB;
        const float* xh  = x + bo * Cc * Nn;
        float* gah = (float*)pga + bo * Cc;
        float* gbh = (float*)pgb + bo * Cc;
        bf16*  xnh = (bf16*)pxn + bo * Nn * Cc;
        bf16*  qkvh= (bf16*)pqkv + bo * C3 * Nn;
        bf16*  Eh  = (bf16*)pE + bo * Nn * Nn;
        float* psh = (float*)pps + bo * Nn * 8;
        bf16*  ath = (bf16*)pattn + bo * Nn * Cc;
        float* outh= out + bo * Cc * Nn;

        gn_stats_kernel<<<HB * 32, 256, 0, st>>>(xh, gns, gnb, gah, gbh);
        gn_apply_t_kernel<<<dim3(32, 16, HB), dim3(32, 8), 0, st>>>(xh, gah, gbh, xnh);
        gemm_bt<0><<<dim3(8, 12, HB), 256, GSMEM, st>>>(
            (const bf16*)pw1, xnh, qkvh, b1, nullptr,
            C3, Nn, Cc, Cc, Cc, Nn, 0L, (long)Nn * Cc, (long)C3 * Nn, 0L);
        s_exp_kernel<<<dim3(8, 8, HB), 256, TSMEM, st>>>(qkvh, Eh, psh);
        gemm_bt<5><<<dim3(4, 8, HB), 256, GSMEM, st>>>(
            Eh, qkvh + (size_t)2 * Cc * Nn, ath, psh, nullptr,
            Nn, Cc, Nn, Nn, Nn, Cc, (long)Nn * Nn, (long)C3 * Nn, (long)Nn * Cc, 0L);
        gemm_bt<3><<<dim3(8, 4, HB), 256, GSMEM, st>>>(
            (const bf16*)pw2, ath, outh, b2, xh,
            Cc, Nn, Cc, Cc, Cc, Nn, 0L, (long)Nn * Cc, (long)Cc * Nn, (long)Cc * Nn);
    }

    // join the forked stream back into the main stream
    cudaEventRecord(evJ, s2);
    cudaStreamWaitEvent(0, evJ, 0);
}